// round 3
// baseline (speedup 1.0000x reference)
#include <cuda_runtime.h>
#include <cuda_fp16.h>
#include <cstdint>

// ---------------------------------------------------------------------------
// DARTSLayer as one fp16 tensor-core GEMM (mma.sync.m16n8k16):
//   out[b,j] = sum_{p,i} W[p*64+i, j] * prim_p(x[b,i])
//   W[k,j]   = softmax(alphas[i,j,:])[p+1] * coeffs[i,j,p+1]  (op 0 = 'none' drops out)
// A (primitives) computed in registers, W pre-packed into mma B-fragments.
// No sm_103a-only instructions (harness ptxas targets plain sm_103).
// ---------------------------------------------------------------------------

#define BATCH   65536
#define NIN     64
#define NOUT    64
#define NKK     28              // K=448 / 16 per mma
#define WFRAG_N (NKK * 8 * 32)  // kk * ntile * lane -> uint2 (b0,b1)
#define SMEM_B  (WFRAG_N * 8)   // 57344 bytes

__device__ uint2 g_Wfrag[WFRAG_N];

// --------------------------- helpers ----------------------------------------

__device__ __forceinline__ uint32_t pack2(float lo, float hi) {
    uint32_t r;
    asm("cvt.rn.f16x2.f32 %0, %1, %2;" : "=r"(r) : "f"(hi), "f"(lo));
    return r;
}

__device__ __forceinline__ float frcp(float x) {
    float r;
    asm("rcp.approx.f32 %0, %1;" : "=f"(r) : "f"(x));
    return r;
}

__device__ __forceinline__ void mma16816(float* d, const uint32_t* a, uint2 b) {
    asm volatile(
        "mma.sync.aligned.m16n8k16.row.col.f32.f16.f16.f32 "
        "{%0,%1,%2,%3}, {%4,%5,%6,%7}, {%8,%9}, {%0,%1,%2,%3};"
        : "+f"(d[0]), "+f"(d[1]), "+f"(d[2]), "+f"(d[3])
        : "r"(a[0]), "r"(a[1]), "r"(a[2]), "r"(a[3]), "r"(b.x), "r"(b.y));
}

__device__ __forceinline__ float prim_eval(int p, float x) {
    switch (p) {
        case 0:  return x;            // linear
        case 1:  return x * x;        // power_two
        case 2:  return x * x * x;    // power_three
        case 3:  return __expf(x);    // exp
        case 4:  return __logf(x);    // ln
        case 5:  return frcp(x);      // reciprocal
        default: return __sinf(x);    // sin
    }
}

// --------------------------- W preparation -----------------------------------
// One thread per (i, j). Computes softmax-gated weights and scatters them as
// fp16 halves directly into the mma B-fragment layout:
//   frag element = ((kk*8 + nt)*32 + lane) -> uint2 {b0, b1}
//   b0 halves: k = 2c, 2c+1 ; b1 halves: k = 2c+8, 2c+9 ; n = lane/4 ; c = lane%4

__global__ void darts_prep_kernel(const float* __restrict__ alphas,
                                  const float* __restrict__ coeffs) {
    int idx = blockIdx.x * blockDim.x + threadIdx.x;  // i*64 + j
    if (idx >= NIN * NOUT) return;
    int i = idx >> 6;
    int j = idx & 63;

    float a[8];
#pragma unroll
    for (int k = 0; k < 8; k++) a[k] = alphas[idx * 8 + k];
    float m = a[0];
#pragma unroll
    for (int k = 1; k < 8; k++) m = fmaxf(m, a[k]);
    float e[8], s = 0.0f;
#pragma unroll
    for (int k = 0; k < 8; k++) { e[k] = __expf(a[k] - m); s += e[k]; }
    float inv = 1.0f / s;

    __half* dst = (__half*)g_Wfrag;
#pragma unroll
    for (int p = 0; p < 7; p++) {
        float wv = e[p + 1] * inv * coeffs[idx * 8 + p + 1];
        int k    = p * 64 + i;
        int kk   = k >> 4;
        int kpos = k & 15;
        int nt   = j >> 3;
        int lane = (j & 7) * 4 + ((kpos & 7) >> 1);
        int reg  = kpos >> 3;
        int half = kpos & 1;
        dst[(((kk * 8 + nt) * 32 + lane) * 2 + reg) * 2 + half] = __float2half_rn(wv);
    }
}

// --------------------------- main GEMM ---------------------------------------
// 128 threads (4 warps). Each warp owns 32 batch rows x all 64 outputs x K=448.
// grid = 512 CTAs (one 128-row tile each).

__global__ void __launch_bounds__(128, 1)
darts_main_kernel(const float* __restrict__ x, float* __restrict__ out) {
    extern __shared__ uint2 sW[];
    int tid  = threadIdx.x;
    int wid  = tid >> 5;
    int lane = tid & 31;
    int r    = lane >> 2;   // 0..7
    int c    = lane & 3;    // 0..3

    // Stage W fragments into SMEM (coalesced uint4 copy, 57344 B)
    {
        const uint4* src = (const uint4*)g_Wfrag;
        uint4* dst = (uint4*)sW;
        for (int u = tid; u < WFRAG_N / 2; u += 128) dst[u] = src[u];
    }

    int warp_row0 = blockIdx.x * 128 + wid * 32;

    // Load this warp's x values: 4 row-slots (l/4 + {0,8,16,24}), 16 i's each,
    // as float2 pairs at even i (matches mma A-fragment k-pair layout).
    float2 xd[4][4][2];
#pragma unroll
    for (int rr = 0; rr < 4; rr++) {
        const float* xrow = x + (size_t)(warp_row0 + rr * 8 + r) * NIN;
#pragma unroll
        for (int q = 0; q < 4; q++) {
            xd[rr][q][0] = *(const float2*)(xrow + q * 16 + 2 * c);
            xd[rr][q][1] = *(const float2*)(xrow + q * 16 + 2 * c + 8);
        }
    }

    float acc[2][8][4];
#pragma unroll
    for (int m = 0; m < 2; m++)
#pragma unroll
        for (int nt = 0; nt < 8; nt++)
#pragma unroll
            for (int v = 0; v < 4; v++) acc[m][nt][v] = 0.0f;

    __syncthreads();   // W staged

#pragma unroll
    for (int p = 0; p < 7; p++) {
#pragma unroll
        for (int q = 0; q < 4; q++) {
            // Build A fragments for both m-tiles (prims of 16 x values)
            uint32_t A[2][4];
#pragma unroll
            for (int rr = 0; rr < 4; rr++) {
#pragma unroll
                for (int h = 0; h < 2; h++) {
                    float2 v = xd[rr][q][h];
                    A[rr >> 1][(rr & 1) + 2 * h] =
                        pack2(prim_eval(p, v.x), prim_eval(p, v.y));
                }
            }
            int kk = p * 4 + q;
            const uint2* bp = sW + (kk * 8) * 32 + lane;
#pragma unroll
            for (int nt = 0; nt < 8; nt++) {
                uint2 b = bp[nt * 32];
                mma16816(acc[0][nt], A[0], b);
                mma16816(acc[1][nt], A[1], b);
            }
        }
    }

    // Write out: c0/c1 -> row l/4, c2/c3 -> row l/4+8, cols nt*8 + 2c, +1
#pragma unroll
    for (int m = 0; m < 2; m++) {
#pragma unroll
        for (int hr = 0; hr < 2; hr++) {
            float* orow = out + (size_t)(warp_row0 + m * 16 + hr * 8 + r) * NOUT;
#pragma unroll
            for (int nt = 0; nt < 8; nt++) {
                float2 v;
                v.x = acc[m][nt][hr * 2 + 0];
                v.y = acc[m][nt][hr * 2 + 1];
                *(float2*)(orow + nt * 8 + 2 * c) = v;
            }
        }
    }
}

// --------------------------- launch ------------------------------------------

extern "C" void kernel_launch(void* const* d_in, const int* in_sizes, int n_in,
                              void* d_out, int out_size) {
    (void)in_sizes; (void)n_in; (void)out_size;
    const float* x      = (const float*)d_in[0];
    const float* alphas = (const float*)d_in[1];
    const float* coeffs = (const float*)d_in[2];

    darts_prep_kernel<<<32, 128>>>(alphas, coeffs);

    cudaFuncSetAttribute(darts_main_kernel,
                         cudaFuncAttributeMaxDynamicSharedMemorySize, SMEM_B);
    darts_main_kernel<<<BATCH / 128, 128, SMEM_B>>>(x, (float*)d_out);
}